// round 3
// baseline (speedup 1.0000x reference)
#include <cuda_runtime.h>

#define NTHREADS 512
#define ROWS_PER_CTA 64
#define NCTA 128          // 8192 / 64
#define OUTSTR 771        // 257*3

struct SMem {
    float4 wpack[76][64];   // wpack[k][u] = {Wi,Wf,Wg,Wo}[.,k] for unit u
    float2 inbuf[76][34];   // [k][pair]; k<12 step input, k>=12 h
    float  w1t[64][64];     // w1t[k][u] = W1[u][k]
    float2 zred[8][2][4];   // [group q][warp half][pair]
};

__device__ __forceinline__ float sigf(float x) {
    return __fdividef(1.f, 1.f + __expf(-x));
}
__device__ __forceinline__ float tanh_(float x) {
    float e = __expf(2.f * x);
    return 1.f - __fdividef(2.f, e + 1.f);
}

// 4 accumulators += pair-vector * scalar, via packed fma.rn.f32x2 (FFMA2)
__device__ __forceinline__ void gate4(float sw,
                                      float2 p0, float2 p1, float2 p2, float2 p3,
                                      float2& a0, float2& a1, float2& a2, float2& a3) {
    asm("{\n\t"
        ".reg .b64 rb, rx, ra;\n\t"
        "mov.b64 rb, {%8,%8};\n\t"
        "mov.b64 rx, {%9,%10};  mov.b64 ra, {%0,%1}; fma.rn.f32x2 ra, rx, rb, ra; mov.b64 {%0,%1}, ra;\n\t"
        "mov.b64 rx, {%11,%12}; mov.b64 ra, {%2,%3}; fma.rn.f32x2 ra, rx, rb, ra; mov.b64 {%2,%3}, ra;\n\t"
        "mov.b64 rx, {%13,%14}; mov.b64 ra, {%4,%5}; fma.rn.f32x2 ra, rx, rb, ra; mov.b64 {%4,%5}, ra;\n\t"
        "mov.b64 rx, {%15,%16}; mov.b64 ra, {%6,%7}; fma.rn.f32x2 ra, rx, rb, ra; mov.b64 {%6,%7}, ra;\n\t"
        "}"
        : "+f"(a0.x), "+f"(a0.y), "+f"(a1.x), "+f"(a1.y),
          "+f"(a2.x), "+f"(a2.y), "+f"(a3.x), "+f"(a3.y)
        : "f"(sw),
          "f"(p0.x), "f"(p0.y), "f"(p1.x), "f"(p1.y),
          "f"(p2.x), "f"(p2.y), "f"(p3.x), "f"(p3.y));
}

__device__ __forceinline__ void lstm_step4(SMem* s, int u, int q,
                                           float bi, float bf, float bg, float bo,
                                           float2 c4[4], float2 h4[4]) {
    float2 ai[4], af4[4], ag[4], ao[4];
#pragma unroll
    for (int p = 0; p < 4; ++p) {
        ai[p] = make_float2(bi, bi);
        af4[p] = make_float2(bf, bf);
        ag[p] = make_float2(bg, bg);
        ao[p] = make_float2(bo, bo);
    }
    const float4* wp = &s->wpack[0][u];
    const float2* xb = &s->inbuf[0][4 * q];
#pragma unroll 4
    for (int k = 0; k < 76; ++k) {
        float4 w = *wp; wp += 64;
        float4 x01 = *reinterpret_cast<const float4*>(xb);
        float4 x23 = *reinterpret_cast<const float4*>(xb + 2);
        xb += 34;
        float2 p0 = make_float2(x01.x, x01.y), p1 = make_float2(x01.z, x01.w);
        float2 p2 = make_float2(x23.x, x23.y), p3 = make_float2(x23.z, x23.w);
        gate4(w.x, p0, p1, p2, p3, ai[0], ai[1], ai[2], ai[3]);
        gate4(w.y, p0, p1, p2, p3, af4[0], af4[1], af4[2], af4[3]);
        gate4(w.z, p0, p1, p2, p3, ag[0], ag[1], ag[2], ag[3]);
        gate4(w.w, p0, p1, p2, p3, ao[0], ao[1], ao[2], ao[3]);
    }
#pragma unroll
    for (int p = 0; p < 4; ++p) {
        float ix = sigf(ai[p].x), fx = sigf(af4[p].x), gx = tanh_(ag[p].x), ox = sigf(ao[p].x);
        c4[p].x = fmaf(fx, c4[p].x, ix * gx);
        h4[p].x = ox * tanh_(c4[p].x);
        float iy = sigf(ai[p].y), fy = sigf(af4[p].y), gy = tanh_(ag[p].y), oy = sigf(ao[p].y);
        c4[p].y = fmaf(fy, c4[p].y, iy * gy);
        h4[p].y = oy * tanh_(c4[p].y);
    }
}

__global__ void __launch_bounds__(NTHREADS, 1)
lstm_fused(const float* __restrict__ noise, const float* __restrict__ hist,
           const float* __restrict__ gap,   const float* __restrict__ W_ih,
           const float* __restrict__ W_hh,  const float* __restrict__ b_ih,
           const float* __restrict__ b_hh,  const float* __restrict__ W1,
           const float* __restrict__ b1,    const float* __restrict__ W2,
           const float* __restrict__ b2,    float* __restrict__ out) {
    extern __shared__ char smraw[];
    SMem* s = reinterpret_cast<SMem*>(smraw);

    const int tid = threadIdx.x;
    const int u = tid & 63;
    const int q = tid >> 6;
    const int lane = tid & 31;
    const int wh = (tid >> 5) & 1;
    const int blockRow = blockIdx.x * ROWS_PER_CTA;
    const int R = blockRow + q * 8;  // this thread's 8 rows: R..R+7

    // ---- stage weights (transposed, gate-packed) ----
    for (int idx = tid; idx < 76 * 64; idx += NTHREADS) {
        int k = idx >> 6, uu = idx & 63;
        float4 w;
        if (k < 12) {
            w.x = W_ih[uu * 12 + k];
            w.y = W_ih[(64 + uu) * 12 + k];
            w.z = W_ih[(128 + uu) * 12 + k];
            w.w = W_ih[(192 + uu) * 12 + k];
        } else {
            int kk = k - 12;
            w.x = W_hh[uu * 64 + kk];
            w.y = W_hh[(64 + uu) * 64 + kk];
            w.z = W_hh[(128 + uu) * 64 + kk];
            w.w = W_hh[(192 + uu) * 64 + kk];
        }
        s->wpack[k][uu] = w;
    }
    for (int idx = tid; idx < 64 * 64; idx += NTHREADS) {
        int uu = idx >> 6, k = idx & 63;
        s->w1t[k][uu] = W1[idx];
    }
    // ---- copy hist_x into out[:, :64, :] ----
    for (int idx = tid; idx < ROWS_PER_CTA * 192; idx += NTHREADS) {
        int rl = idx / 192, j = idx % 192;
        out[(size_t)(blockRow + rl) * OUTSTR + j] = hist[(size_t)(blockRow + rl) * 192 + j];
    }
    // h0 = 0
#pragma unroll
    for (int p = 0; p < 4; ++p) s->inbuf[12 + u][4 * q + p] = make_float2(0.f, 0.f);

    const float bi = b_ih[u] + b_hh[u];
    const float bf = b_ih[64 + u] + b_hh[64 + u];
    const float bg = b_ih[128 + u] + b_hh[128 + u];
    const float bo = b_ih[192 + u] + b_hh[192 + u];
    const float b1v = b1[u];
    const float w2v = W2[u];
    const float b2v = b2[0];

    float2 c4[4], h4[4], dist4[4], pfv[4];
#pragma unroll
    for (int p = 0; p < 4; ++p) {
        c4[p] = make_float2(0.f, 0.f);
        dist4[p] = make_float2(0.f, 0.f);
        pfv[p] = make_float2(0.f, 0.f);
    }

    auto pre_cond = [&](int j) {
        if (u < 4) {
            int ch = (u == 3) ? 2 : u;
#pragma unroll
            for (int p = 0; p < 4; ++p) {
                const float* hp = hist + (size_t)(R + 2 * p) * 192 + j * 3 + ch;
                pfv[p].x = hp[0];
                pfv[p].y = hp[192];
            }
        } else if (u < 12) {
            int ch = u - 4;
#pragma unroll
            for (int p = 0; p < 4; ++p) {
                const float* np = noise + (size_t)(R + 2 * p) * 2048 + j * 8 + ch;
                pfv[p].x = np[0];
                pfv[p].y = np[2048];
            }
        }
    };
    auto pre_gen = [&](int t) {
        if (u < 2) {
#pragma unroll
            for (int p = 0; p < 4; ++p) {
                const float* gp = gap + (size_t)(R + 2 * p) * 386 + t * 2 + u;
                pfv[p].x = gp[0];
                pfv[p].y = gp[386];
            }
        } else if (u >= 4 && u < 12) {
            if (t < 192) {
                int ch = u - 4;
#pragma unroll
                for (int p = 0; p < 4; ++p) {
                    const float* np = noise + (size_t)(R + 2 * p) * 2048 + (64 + t) * 8 + ch;
                    pfv[p].x = np[0];
                    pfv[p].y = np[2048];
                }
            } else {
#pragma unroll
                for (int p = 0; p < 4; ++p) pfv[p] = make_float2(0.f, 0.f);
            }
        }
    };

    pre_cond(0);
    __syncthreads();  // staging + h0 visible

    // ================= conditioning (64 steps) =================
    for (int j = 0; j < 64; ++j) {
        if (u == 3) {
#pragma unroll
            for (int p = 0; p < 4; ++p) {
                dist4[p].x += pfv[p].x;
                dist4[p].y += pfv[p].y;
                s->inbuf[3][4 * q + p] = dist4[p];
            }
        } else if (u < 12) {
#pragma unroll
            for (int p = 0; p < 4; ++p) s->inbuf[u][4 * q + p] = pfv[p];
        }
        __syncthreads();
        if (j < 63) pre_cond(j + 1); else pre_gen(0);
        lstm_step4(s, u, q, bi, bf, bg, bo, c4, h4);
        __syncthreads();
#pragma unroll
        for (int p = 0; p < 4; ++p) s->inbuf[12 + u][4 * q + p] = h4[p];
        __syncthreads();
    }

    // ================= generation (193 steps) =================
    for (int t = 0; t <= 192; ++t) {
        // --- MLP head: a1[u] = b1 + sum_k h[k]*W1[u][k] ---
        float2 a0 = make_float2(b1v, b1v), a1v = a0, a2 = a0, a3 = a0;
        const float* w1p = &s->w1t[0][u];
        const float2* xb = &s->inbuf[12][4 * q];
#pragma unroll 4
        for (int k = 0; k < 64; ++k) {
            float wv = *w1p; w1p += 64;
            float4 x01 = *reinterpret_cast<const float4*>(xb);
            float4 x23 = *reinterpret_cast<const float4*>(xb + 2);
            xb += 34;
            gate4(wv, make_float2(x01.x, x01.y), make_float2(x01.z, x01.w),
                  make_float2(x23.x, x23.y), make_float2(x23.z, x23.w),
                  a0, a1v, a2, a3);
        }
        float2 part[4];
        part[0] = make_float2(tanh_(a0.x) * w2v, tanh_(a0.y) * w2v);
        part[1] = make_float2(tanh_(a1v.x) * w2v, tanh_(a1v.y) * w2v);
        part[2] = make_float2(tanh_(a2.x) * w2v, tanh_(a2.y) * w2v);
        part[3] = make_float2(tanh_(a3.x) * w2v, tanh_(a3.y) * w2v);
#pragma unroll
        for (int p = 0; p < 4; ++p) {
#pragma unroll
            for (int m = 16; m >= 1; m >>= 1) {
                part[p].x += __shfl_xor_sync(0xffffffffu, part[p].x, m);
                part[p].y += __shfl_xor_sync(0xffffffffu, part[p].y, m);
            }
        }
        if (lane == 0) {
#pragma unroll
            for (int p = 0; p < 4; ++p) s->zred[q][wh][p] = part[p];
        }
        __syncthreads();  // A: zred visible; MLP reads of h done

        if (u < 12) {
            int trow = (64 + t) * 3;
            float2 dp[4];
#pragma unroll
            for (int p = 0; p < 4; ++p) {
                float2 za = s->zred[q][0][p];
                float2 zb = s->zred[q][1][p];
                dp[p].x = 24.f * tanh_(za.x + zb.x + b2v);
                dp[p].y = 24.f * tanh_(za.y + zb.y + b2v);
            }
            if (u < 2) {
#pragma unroll
                for (int p = 0; p < 4; ++p) {
                    s->inbuf[u][4 * q + p] = pfv[p];
                    out[(size_t)(R + 2 * p) * OUTSTR + trow + u] = pfv[p].x;
                    out[(size_t)(R + 2 * p + 1) * OUTSTR + trow + u] = pfv[p].y;
                }
            } else if (u == 2) {
#pragma unroll
                for (int p = 0; p < 4; ++p) {
                    s->inbuf[2][4 * q + p] = dp[p];
                    out[(size_t)(R + 2 * p) * OUTSTR + trow + 2] = dp[p].x;
                    out[(size_t)(R + 2 * p + 1) * OUTSTR + trow + 2] = dp[p].y;
                }
            } else if (u == 3) {
#pragma unroll
                for (int p = 0; p < 4; ++p) {
                    dist4[p].x += dp[p].x;
                    dist4[p].y += dp[p].y;
                    s->inbuf[3][4 * q + p] = dist4[p];
                }
            } else {
#pragma unroll
                for (int p = 0; p < 4; ++p) s->inbuf[u][4 * q + p] = pfv[p];
            }
        }
        if (t == 192) break;  // last step's LSTM update is dead in the reference
        __syncthreads();  // B: inputs visible
        pre_gen(t + 1);
        lstm_step4(s, u, q, bi, bf, bg, bo, c4, h4);
        __syncthreads();  // C: gate reads done
#pragma unroll
        for (int p = 0; p < 4; ++p) s->inbuf[12 + u][4 * q + p] = h4[p];
        __syncthreads();  // D: h visible
    }
}

extern "C" void kernel_launch(void* const* d_in, const int* in_sizes, int n_in,
                              void* d_out, int out_size) {
    const float* noise = (const float*)d_in[0];
    const float* hist  = (const float*)d_in[1];
    const float* gap   = (const float*)d_in[2];
    const float* W_ih  = (const float*)d_in[3];
    const float* W_hh  = (const float*)d_in[4];
    const float* b_ih  = (const float*)d_in[5];
    const float* b_hh  = (const float*)d_in[6];
    const float* W1    = (const float*)d_in[7];
    const float* b1    = (const float*)d_in[8];
    const float* W2    = (const float*)d_in[9];
    const float* b2    = (const float*)d_in[10];
    float* out = (float*)d_out;

    size_t smem = sizeof(SMem);
    cudaFuncSetAttribute(lstm_fused, cudaFuncAttributeMaxDynamicSharedMemorySize, (int)smem);
    lstm_fused<<<NCTA, NTHREADS, smem>>>(noise, hist, gap, W_ih, W_hh, b_ih, b_hh,
                                         W1, b1, W2, b2, out);
}